// round 8
// baseline (speedup 1.0000x reference)
#include <cuda_runtime.h>
#include <math.h>

#define DINLINE __device__ __forceinline__

// ---------------- problem constants ----------------
#define Bb 8
#define Hh 128
#define Ww 128
#define Cc 96
#define Mm 192
#define SPEC (128*65)
#define INV_HW (1.0f/16384.0f)

// ---------------- device scratch ----------------
__device__ float  g_xpre[(size_t)Bb*Mm*Hh*Ww];     // reused in-place for xsp
__device__ float2 g_filt[(size_t)3*Mm*SPEC];       // resized filters (BR h order)
__device__ float2 g_tmp[(size_t)48*65*Mm];         // separable-resize intermediate
__device__ float  g_r[Bb*3*Mm];
__device__ float  g_stats[Bb*144];
// tf32-split weights: rows 0..191 = w1, rows 192..239 = spw
__device__ float  g_w1hi[240*96], g_w1lo[240*96];
__device__ float  g_w2hi[96*192], g_w2lo[96*192];

extern __shared__ __align__(16) char SMEM[];

// ---------------- helpers ----------------
DINLINE int br7(int p){ return (int)(__brev((unsigned)p)>>25); }
DINLINE float2 cmulf(float2 a, float2 b){ return make_float2(a.x*b.x - a.y*b.y, a.x*b.y + a.y*b.x); }
DINLINE float2 f2add(float2 a,float2 b){ return make_float2(a.x+b.x, a.y+b.y); }
DINLINE float2 f2sub(float2 a,float2 b){ return make_float2(a.x-b.x, a.y-b.y); }
DINLINE float2 shflx(float2 v,int m){
    v.x = __shfl_xor_sync(0xffffffffu, v.x, m);
    v.y = __shfl_xor_sync(0xffffffffu, v.y, m);
    return v;
}
// tf32 helpers
DINLINE unsigned f2tf(float x){ unsigned r; asm("cvt.rna.tf32.f32 %0,%1;":"=r"(r):"f"(x)); return r; }
DINLINE void tfsplit(float x, unsigned& hi, unsigned& lo){
    hi = f2tf(x);
    lo = f2tf(x - __uint_as_float(hi));
}
DINLINE void mma8(float c[4], const unsigned a[4], unsigned b0, unsigned b1){
    asm("mma.sync.aligned.m16n8k8.row.col.f32.tf32.tf32.f32 "
        "{%0,%1,%2,%3},{%4,%5,%6,%7},{%8,%9},{%0,%1,%2,%3};"
        : "+f"(c[0]),"+f"(c[1]),"+f"(c[2]),"+f"(c[3])
        : "r"(a[0]),"r"(a[1]),"r"(a[2]),"r"(a[3]),"r"(b0),"r"(b1));
}

// Forward DIF 128-pt FFT: natural input at p=j*32+lane -> X[br7(p)] at p.
DINLINE void fft128_dif(float2 z[4], const float2* tw, int lane){
    #pragma unroll
    for(int j=0;j<2;j++){
        int k=j*32+lane;
        float2 u=z[j], v=z[j+2];
        z[j]=f2add(u,v);
        z[j+2]=cmulf(f2sub(u,v), tw[k]);
    }
    {
        float2 w=tw[2*lane];
        float2 u=z[0],v=z[1];
        z[0]=f2add(u,v); z[1]=cmulf(f2sub(u,v),w);
        u=z[2]; v=z[3];
        z[2]=f2add(u,v); z[3]=cmulf(f2sub(u,v),w);
    }
    #pragma unroll
    for(int d=16; d>=1; d>>=1){
        int k=lane&(d-1);
        float2 w=tw[k*(64/d)];
        bool up=(lane&d)!=0;
        #pragma unroll
        for(int j=0;j<4;j++){
            float2 o=shflx(z[j],d);
            float2 r;
            if(up) r=cmulf(make_float2(o.x - z[j].x, o.y - z[j].y), w);
            else   r=make_float2(z[j].x+o.x, z[j].y+o.y);
            z[j]=r;
        }
    }
}

// DIT 128-pt FFT: bit-reversed input at p -> natural output at p.
template<bool CONJ>
DINLINE void fft128_dit(float2 z[4], const float2* tw, int lane){
    #pragma unroll
    for(int d=1; d<=16; d<<=1){
        int k=lane&(d-1);
        float2 w=tw[k*(64/d)];
        if(CONJ) w.y=-w.y;
        bool up=(lane&d)!=0;
        #pragma unroll
        for(int j=0;j<4;j++){
            float2 o=shflx(z[j],d);
            float2 r;
            if(up){
                float2 t=cmulf(w, z[j]);
                r=make_float2(o.x-t.x, o.y-t.y);
            } else {
                float2 t=cmulf(w, o);
                r=make_float2(z[j].x+t.x, z[j].y+t.y);
            }
            z[j]=r;
        }
    }
    {
        float2 w=tw[2*lane]; if(CONJ) w.y=-w.y;
        float2 t=cmulf(w,z[1]); float2 u=z[0];
        z[0]=f2add(u,t); z[1]=f2sub(u,t);
        t=cmulf(w,z[3]); u=z[2];
        z[2]=f2add(u,t); z[3]=f2sub(u,t);
    }
    #pragma unroll
    for(int j=0;j<2;j++){
        int k=j*32+lane;
        float2 w=tw[k]; if(CONJ) w.y=-w.y;
        float2 t=cmulf(w,z[j+2]); float2 u=z[j];
        z[j]=f2add(u,t);
        z[j+2]=f2sub(u,t);
    }
}

// ---------------- bicubic resize taps (match reference) ----------------
DINLINE double cubicw(double t){
    t = fabs(t);
    const double a = -0.75;
    if(t <= 1.0) return ((a+2.0)*t - (a+3.0))*t*t + 1.0;
    if(t <  2.0) return a*(((t-5.0)*t+8.0)*t-4.0);
    return 0.0;
}
DINLINE void taps4(int j, int oldn, int newn, int* idx, float* wt){
    double s = (newn > 1) ? (double)j * (double)(oldn-1) / (double)(newn-1) : 0.0;
    int f = (int)floor(s);
    #pragma unroll
    for(int k=0;k<4;k++){
        int kk = f + k - 1;
        idx[k] = min(max(kk, 0), oldn-1);
        wt[k]  = (float)cubicw(s - (double)kk);
    }
}

// scale tables
__constant__ int c_SH[3]={16,8,24};
__constant__ int c_SW[3]={9,4,13};
__constant__ int c_RB[3]={0,16,24};   // row base in g_tmp

// ---------------- k_prep: tf32 split of w1/spw and w2 ----------------
__global__ void __launch_bounds__(256) k_prep(const float* __restrict__ w1,
                                              const float* __restrict__ spw,
                                              const float* __restrict__ w2){
    int tid=blockIdx.x*256+threadIdx.x;
    for(int i=tid;i<240*96;i+=256*32){
        int n=i/96, k=i%96;
        float w = (n<192)? w1[n*96+k] : spw[(n-192)*96+k];
        unsigned hi,lo; tfsplit(w,hi,lo);
        g_w1hi[i]=__uint_as_float(hi);
        g_w1lo[i]=__uint_as_float(lo);
    }
    for(int i=tid;i<96*192;i+=256*32){
        float w = w2[i];
        unsigned hi,lo; tfsplit(w,hi,lo);
        g_w2hi[i]=__uint_as_float(hi);
        g_w2lo[i]=__uint_as_float(lo);
    }
}

// ---------------- k_filt1 ----------------
__global__ void __launch_bounds__(256) k_filt1(const float* __restrict__ cw0,
                                               const float* __restrict__ cw1,
                                               const float* __restrict__ cw2){
    __shared__ int   widx[65][4];
    __shared__ float wwt [65][4];
    __shared__ float2 rowb[13*Mm];
    int r = blockIdx.x;
    int s = (r<16)?0:((r<24)?1:2);
    int ih = r - c_RB[s];
    int ow = c_SW[s];
    const float* cws = (s==0)?cw0:((s==1)?cw1:cw2);
    int tid=threadIdx.x;
    if(tid<65) taps4(tid, ow, 65, widx[tid], wwt[tid]);
    const float2* src = (const float2*)(cws) + (size_t)ih*ow*Mm;
    for(int i=tid;i<ow*Mm;i+=256) rowb[i]=src[i];
    __syncthreads();
    float2* dst = g_tmp + (size_t)r*65*Mm;
    for(int e=tid;e<65*Mm;e+=256){
        int w=e/Mm, m=e%Mm;
        float ax=0.f, ay=0.f;
        #pragma unroll
        for(int a=0;a<4;a++){
            float wg=wwt[w][a];
            float2 v=rowb[widx[w][a]*Mm+m];
            ax+=wg*v.x; ay+=wg*v.y;
        }
        dst[e]=make_float2(ax,ay);
    }
}

// ---------------- k_filt2 ----------------
__global__ void __launch_bounds__(128) k_filt2(){
    __shared__ int   hidx[4];
    __shared__ float hwt [4];
    __shared__ float2 tile[48*65];
    int bid=blockIdx.x;
    int s  = bid/512;
    int rem= bid%512;
    int hq = rem/4;
    int m0 = (rem%4)*48;
    int tid=threadIdx.x;
    if(tid==0){
        int id[4]; float wt[4];
        taps4(hq, c_SH[s], 128, id, wt);
        #pragma unroll
        for(int a=0;a<4;a++){ hidx[a]=id[a]; hwt[a]=wt[a]; }
    }
    __syncthreads();
    const float2* base = g_tmp + (size_t)c_RB[s]*65*Mm;
    for(int e=tid;e<65*48;e+=128){
        int w=e/48, mm=e%48;
        int m=m0+mm;
        float ax=0.f, ay=0.f;
        #pragma unroll
        for(int a=0;a<4;a++){
            float2 v=base[(size_t)hidx[a]*65*Mm + w*Mm + m];
            ax+=hwt[a]*v.x; ay+=hwt[a]*v.y;
        }
        tile[mm*65+w]=make_float2(ax,ay);
    }
    __syncthreads();
    int hb=br7(hq);
    for(int e=tid;e<48*65;e+=128){
        int mm=e/65, w=e%65;
        g_filt[(size_t)(s*Mm+m0+mm)*SPEC + hb*65 + w]=tile[mm*65+w];
    }
}

// ---------------- k_zero ----------------
__global__ void k_zero(){
    for(int i=threadIdx.x;i<Bb*144;i+=blockDim.x) g_stats[i]=0.f;
}

// ---------------- k_pw1: tf32 MMA pwconv1+Soa + routing stats ----------------
// smem floats: xs[128*100]=12800, wsh[240*52]=12480, wsl[240*52]=12480,
//              sctxbuf[48*132]=6336, bnp[96], red[192]
#define P1_XS  0
#define P1_WH  (P1_XS+12800)
#define P1_WL  (P1_WH+12480)
#define P1_SB  (P1_WL+12480)
#define P1_BNP (P1_SB+6336)
#define P1_RED (P1_BNP+96)
#define P1_TOT (P1_RED+192)
__global__ void __launch_bounds__(256) k_pw1(const float* __restrict__ x,
                                             const float* __restrict__ s1,
                                             const float* __restrict__ b1,
                                             const float* __restrict__ bng,
                                             const float* __restrict__ bnb,
                                             const float* __restrict__ bnm,
                                             const float* __restrict__ bnv){
    float* S=(float*)SMEM;
    float* xs  = S+P1_XS;      // [128][100]
    float* wsh = S+P1_WH;      // [240][52] (k-half)
    float* wsl = S+P1_WL;
    float* sb  = S+P1_SB;      // [48][132]
    float* bnp = S+P1_BNP;
    float* red = S+P1_RED;
    int tid=threadIdx.x;
    int b=blockIdx.y, pix0=blockIdx.x*128;
    const float* xb = x + ((size_t)b*16384 + pix0)*96;
    for(int i=tid;i<128*96;i+=256){ int p=i/96,c=i%96; xs[p*100+c]=xb[i]; }
    if(tid<48){
        float sc=rsqrtf(bnv[tid]+1e-5f)*bng[tid];
        bnp[tid]=sc;
        bnp[48+tid]=bnb[tid]-bnm[tid]*sc;
    }
    int warp=tid>>5, lane=tid&31;
    int gid=lane>>2, tig=lane&3;
    int pr0=warp*16;
    float C[30][4];
    #pragma unroll
    for(int n=0;n<30;n++){ C[n][0]=0.f;C[n][1]=0.f;C[n][2]=0.f;C[n][3]=0.f; }
    for(int kh=0;kh<2;kh++){
        __syncthreads();
        for(int i=tid;i<240*48;i+=256){
            int n=i/48, kk=i%48;
            wsh[n*52+kk]=g_w1hi[n*96 + kh*48 + kk];
            wsl[n*52+kk]=g_w1lo[n*96 + kh*48 + kk];
        }
        __syncthreads();
        unsigned ah[6][4], al[6][4];
        #pragma unroll
        for(int kt=0;kt<6;kt++){
            int k0=kh*48+kt*8;
            float r0=xs[(pr0+gid  )*100 + k0+tig];
            float r1=xs[(pr0+gid+8)*100 + k0+tig];
            float r2=xs[(pr0+gid  )*100 + k0+tig+4];
            float r3=xs[(pr0+gid+8)*100 + k0+tig+4];
            tfsplit(r0,ah[kt][0],al[kt][0]);
            tfsplit(r1,ah[kt][1],al[kt][1]);
            tfsplit(r2,ah[kt][2],al[kt][2]);
            tfsplit(r3,ah[kt][3],al[kt][3]);
        }
        #pragma unroll 1
        for(int n=0;n<30;n++){
            int nrow=(n*8+gid)*52;
            #pragma unroll
            for(int kt=0;kt<6;kt++){
                int kk=kt*8;
                unsigned b0h=__float_as_uint(wsh[nrow+kk+tig]);
                unsigned b1h=__float_as_uint(wsh[nrow+kk+tig+4]);
                unsigned b0l=__float_as_uint(wsl[nrow+kk+tig]);
                unsigned b1l=__float_as_uint(wsl[nrow+kk+tig+4]);
                mma8(C[n], ah[kt], b0h, b1h);
                mma8(C[n], al[kt], b0h, b1h);
                mma8(C[n], ah[kt], b0l, b1l);
            }
        }
    }
    // writeback m<192 with Soa
    float scb=*s1, bib=*b1;
    #pragma unroll 1
    for(int n=0;n<24;n++){
        int mch=n*8+2*tig;
        int px=pix0+pr0+gid;
        float v0=fmaxf(C[n][0],0.f), v1=fmaxf(C[n][1],0.f);
        float v2=fmaxf(C[n][2],0.f), v3=fmaxf(C[n][3],0.f);
        g_xpre[((size_t)(b*Mm+mch  ))*16384 + px  ]=scb*v0*v0+bib;
        g_xpre[((size_t)(b*Mm+mch+1))*16384 + px  ]=scb*v1*v1+bib;
        g_xpre[((size_t)(b*Mm+mch  ))*16384 + px+8]=scb*v2*v2+bib;
        g_xpre[((size_t)(b*Mm+mch+1))*16384 + px+8]=scb*v3*v3+bib;
    }
    // sctx rows -> staging buffer
    #pragma unroll
    for(int n=24;n<30;n++){
        int sc=(n-24)*8+2*tig;
        int p=pr0+gid;
        sb[sc*132+p]      =C[n][0];
        sb[(sc+1)*132+p]  =C[n][1];
        sb[sc*132+p+8]    =C[n][2];
        sb[(sc+1)*132+p+8]=C[n][3];
    }
    // gctx
    float gsum=0.f;
    if(tid<96){
        #pragma unroll 4
        for(int p=0;p<128;p++) gsum+=xs[p*100+tid];
    }
    __syncthreads();
    if(tid<96) atomicAdd(&g_stats[b*144+tid], gsum);
    if(tid<192){
        int sc=tid>>2, q=tid&3;
        float scale=bnp[sc], shift=bnp[48+sc];
        float s=0.f;
        #pragma unroll 4
        for(int p=q*32;p<q*32+32;p++) s+=fmaxf(sb[sc*132+p]*scale+shift,0.f);
        red[sc*4+q]=s;
    }
    __syncthreads();
    if(tid<48) atomicAdd(&g_stats[b*144+96+tid], red[4*tid]+red[4*tid+1]+red[4*tid+2]+red[4*tid+3]);
}

// ---------------- k_mlp ----------------
#define MLP_SF   0
#define MLP_FC1  (8*145)
#define MLP_HM   (MLP_FC1+36*145)
#define MLP_FC2  (MLP_HM+8*37)
#define MLP_TOT  (MLP_FC2+576*37)
__global__ void __launch_bounds__(512) k_mlp(const float* __restrict__ fc1,
                                             const float* __restrict__ fc2,
                                             const float* __restrict__ msc,
                                             const float* __restrict__ mbi){
    float* S=(float*)SMEM;
    float* sf  = S+MLP_SF;
    float* f1s = S+MLP_FC1;
    float* hm  = S+MLP_HM;
    float* f2s = S+MLP_FC2;
    int tid=threadIdx.x;
    for(int i=tid;i<8*144;i+=512){ int b=i/144,k=i%144; sf[b*145+k]=g_stats[i]*(1.f/16384.f); }
    for(int i=tid;i<36*144;i+=512){ int j=i/144,k=i%144; f1s[j*145+k]=fc1[i]; }
    for(int i=tid;i<576*36;i+=512){ int j=i/36,k=i%36; f2s[j*37+k]=fc2[i]; }
    __syncthreads();
    if(tid<288){
        int b=tid/36, j=tid%36;
        float a=0.f;
        #pragma unroll 8
        for(int k=0;k<144;k++) a+=sf[b*145+k]*f1s[j*145+k];
        float r=fmaxf(a,0.f);
        hm[b*37+j]=(*msc)*r*r + (*mbi);
    }
    __syncthreads();
    for(int idx=tid; idx<8*Mm; idx+=512){
        int b=idx/Mm, m=idx%Mm;
        float lg[3];
        #pragma unroll
        for(int s=0;s<3;s++){
            float a=0.f;
            const float* f2=f2s+(size_t)(s*Mm+m)*37;
            #pragma unroll
            for(int k=0;k<36;k++) a+=hm[b*37+k]*f2[k];
            lg[s]=a;
        }
        float mx=fmaxf(lg[0],fmaxf(lg[1],lg[2]));
        float e0=expf(lg[0]-mx), e1=expf(lg[1]-mx), e2=expf(lg[2]-mx);
        float inv=1.f/(e0+e1+e2);
        g_r[(b*3+0)*Mm+m]=e0*inv;
        g_r[(b*3+1)*Mm+m]=e1*inv;
        g_r[(b*3+2)*Mm+m]=e2*inv;
    }
}

// ---------------- k_fft (512 thr) ----------------
__global__ void __launch_bounds__(512) k_fft(){
    float2* sh=(float2*)SMEM;
    float2* sm = sh;                 // 8320
    float2* tmpAll = sh + SPEC;      // 16*128
    float2* tw = sh + SPEC + 2048;   // 64
    int tid=threadIdx.x, lane=tid&31, wid=tid>>5;
    int bm=blockIdx.x;
    int b=bm/Mm, m=bm%Mm;
    float* plane = g_xpre + (size_t)bm*16384;
    if(tid<64){
        float s,c;
        sincospif((float)tid*(1.0f/64.0f), &s, &c);
        tw[tid]=make_float2(c,-s);
    }
    __syncthreads();
    float2* tmp = tmpAll + wid*128;
    for(int pr=wid; pr<64; pr+=16){
        int ra=2*pr, rb=ra+1;
        float2 z[4];
        #pragma unroll
        for(int j=0;j<4;j++){
            int p=j*32+lane, q=br7(p);
            z[j]=make_float2(plane[ra*128+q], plane[rb*128+q]);
        }
        fft128_dit<false>(z,tw,lane);
        #pragma unroll
        for(int j=0;j<4;j++) tmp[j*32+lane]=z[j];
        __syncwarp();
        #pragma unroll
        for(int t=0;t<2;t++){
            int k=t*32+lane;
            float2 Zk=tmp[k], Zc=tmp[(128-k)&127];
            sm[ra*65+k]=make_float2(0.5f*(Zk.x+Zc.x), 0.5f*(Zk.y-Zc.y));
            sm[rb*65+k]=make_float2(0.5f*(Zk.y+Zc.y), 0.5f*(Zc.x-Zk.x));
        }
        if(lane==0){
            float2 Zk=tmp[64];
            sm[ra*65+64]=make_float2(Zk.x,0.f);
            sm[rb*65+64]=make_float2(Zk.y,0.f);
        }
        __syncwarp();
    }
    __syncthreads();
    for(int col=wid; col<65; col+=16){
        float2 z[4];
        #pragma unroll
        for(int j=0;j<4;j++) z[j]=sm[(j*32+lane)*65+col];
        fft128_dif(z,tw,lane);
        #pragma unroll
        for(int j=0;j<4;j++) sm[(j*32+lane)*65+col]=z[j];
    }
    __syncthreads();
    {
        float r0=g_r[(b*3+0)*Mm+m], r1=g_r[(b*3+1)*Mm+m], r2=g_r[(b*3+2)*Mm+m];
        const float2* f0=g_filt + (size_t)(0*Mm+m)*SPEC;
        const float2* f1=g_filt + (size_t)(1*Mm+m)*SPEC;
        const float2* f2=g_filt + (size_t)(2*Mm+m)*SPEC;
        for(int e=tid;e<SPEC;e+=512){
            float2 a=f0[e], bb=f1[e], c=f2[e];
            float2 comb=make_float2(a.x*r0+bb.x*r1+c.x*r2, a.y*r0+bb.y*r1+c.y*r2);
            sm[e]=cmulf(sm[e],comb);
        }
    }
    __syncthreads();
    for(int col=wid; col<65; col+=16){
        float2 z[4];
        #pragma unroll
        for(int j=0;j<4;j++) z[j]=sm[(j*32+lane)*65+col];
        fft128_dit<true>(z,tw,lane);
        #pragma unroll
        for(int j=0;j<4;j++) sm[(j*32+lane)*65+col]=z[j];
    }
    __syncthreads();
    for(int pr=wid; pr<64; pr+=16){
        int ra=2*pr, rb=ra+1;
        float2 z[4];
        #pragma unroll
        for(int j=0;j<4;j++){
            int p=j*32+lane, k=br7(p);
            float2 zz;
            if(k<=64){
                float2 a=sm[ra*65+k], bb=sm[rb*65+k];
                if(k==0||k==64){ a.y=0.f; bb.y=0.f; }
                zz=make_float2(a.x-bb.y, a.y+bb.x);
            } else {
                int kk=128-k;
                float2 a=sm[ra*65+kk], bb=sm[rb*65+kk];
                zz=make_float2(a.x+bb.y, bb.x-a.y);
            }
            z[j]=zz;
        }
        fft128_dit<true>(z,tw,lane);
        #pragma unroll
        for(int j=0;j<4;j++){
            int p=j*32+lane;
            plane[ra*128+p]=z[j].x*INV_HW;
            plane[rb*128+p]=z[j].y*INV_HW;
        }
    }
}

// ---------------- k_pw2: tf32 MMA pwconv2 ----------------
// smem floats: As[128*196]=25088, wh[96*100]=9600, wl[96*100]=9600
#define P2_AS  0
#define P2_WH  (P2_AS+25088)
#define P2_WL  (P2_WH+9600)
#define P2_TOT (P2_WL+9600)
__global__ void __launch_bounds__(256) k_pw2(float* __restrict__ out){
    float* S=(float*)SMEM;
    float* As = S+P2_AS;      // [128][196] k-major (k=m)
    float* wh = S+P2_WH;      // [96][100] per k-half
    float* wl = S+P2_WL;
    int tid=threadIdx.x;
    int b=blockIdx.y, pix0=blockIdx.x*128;
    const float* ap = g_xpre + (size_t)b*Mm*16384 + pix0;
    for(int i=tid;i<192*128;i+=256){
        int mm=i>>7, p=i&127;
        As[p*196+mm]=ap[(size_t)mm*16384+p];
    }
    int warp=tid>>5, lane=tid&31;
    int gid=lane>>2, tig=lane&3;
    int pr0=warp*16;
    float C[12][4];
    #pragma unroll
    for(int n=0;n<12;n++){ C[n][0]=0.f;C[n][1]=0.f;C[n][2]=0.f;C[n][3]=0.f; }
    for(int kh=0;kh<2;kh++){
        __syncthreads();
        for(int i=tid;i<96*96;i+=256){
            int c=i/96, kk=i%96;
            wh[c*100+kk]=g_w2hi[c*192 + kh*96 + kk];
            wl[c*100+kk]=g_w2lo[c*192 + kh*96 + kk];
        }
        __syncthreads();
        unsigned ah[12][4], al[12][4];
        #pragma unroll
        for(int kt=0;kt<12;kt++){
            int k0=kh*96+kt*8;
            float r0=As[(pr0+gid  )*196 + k0+tig];
            float r1=As[(pr0+gid+8)*196 + k0+tig];
            float r2=As[(pr0+gid  )*196 + k0+tig+4];
            float r3=As[(pr0+gid+8)*196 + k0+tig+4];
            tfsplit(r0,ah[kt][0],al[kt][0]);
            tfsplit(r1,ah[kt][1],al[kt][1]);
            tfsplit(r2,ah[kt][2],al[kt][2]);
            tfsplit(r3,ah[kt][3],al[kt][3]);
        }
        #pragma unroll 1
        for(int n=0;n<12;n++){
            int nrow=(n*8+gid)*100;
            #pragma unroll
            for(int kt=0;kt<12;kt++){
                int kk=kt*8;
                unsigned b0h=__float_as_uint(wh[nrow+kk+tig]);
                unsigned b1h=__float_as_uint(wh[nrow+kk+tig+4]);
                unsigned b0l=__float_as_uint(wl[nrow+kk+tig]);
                unsigned b1l=__float_as_uint(wl[nrow+kk+tig+4]);
                mma8(C[n], ah[kt], b0h, b1h);
                mma8(C[n], al[kt], b0h, b1h);
                mma8(C[n], ah[kt], b0l, b1l);
            }
        }
    }
    // writeback out[b][pix][c], c pairs contiguous -> float2
    #pragma unroll
    for(int n=0;n<12;n++){
        int c0=n*8+2*tig;
        int px=pix0+pr0+gid;
        float2* o0=(float2*)(out + ((size_t)b*16384+px  )*96 + c0);
        float2* o1=(float2*)(out + ((size_t)b*16384+px+8)*96 + c0);
        *o0=make_float2(C[n][0],C[n][1]);
        *o1=make_float2(C[n][2],C[n][3]);
    }
}

// ---------------- launch ----------------
extern "C" void kernel_launch(void* const* d_in, const int* in_sizes, int n_in,
                              void* d_out, int out_size){
    (void)in_sizes; (void)n_in; (void)out_size;
    const float* x   =(const float*)d_in[0];
    const float* w1  =(const float*)d_in[1];
    const float* s1  =(const float*)d_in[2];
    const float* b1  =(const float*)d_in[3];
    const float* cw0 =(const float*)d_in[4];
    const float* cw1 =(const float*)d_in[5];
    const float* cw2 =(const float*)d_in[6];
    const float* spw =(const float*)d_in[7];
    const float* bng =(const float*)d_in[8];
    const float* bnb =(const float*)d_in[9];
    const float* bnm =(const float*)d_in[10];
    const float* bnv =(const float*)d_in[11];
    const float* fc1 =(const float*)d_in[12];
    const float* msc =(const float*)d_in[13];
    const float* mbi =(const float*)d_in[14];
    const float* fc2 =(const float*)d_in[15];
    const float* w2  =(const float*)d_in[16];
    float* out=(float*)d_out;

    const int SM_PW1 = P1_TOT*4;                 // ~177.5 KB
    const int SM_FFT = (SPEC+2048+64)*8;         // 83456
    const int SM_PW2 = P2_TOT*4;                 // ~177.2 KB
    const int SM_MLP = MLP_TOT*4;

    cudaFuncSetAttribute(k_pw1, cudaFuncAttributeMaxDynamicSharedMemorySize, SM_PW1);
    cudaFuncSetAttribute(k_fft, cudaFuncAttributeMaxDynamicSharedMemorySize, SM_FFT);
    cudaFuncSetAttribute(k_pw2, cudaFuncAttributeMaxDynamicSharedMemorySize, SM_PW2);
    cudaFuncSetAttribute(k_mlp, cudaFuncAttributeMaxDynamicSharedMemorySize, SM_MLP);

    k_prep<<<32, 256>>>(w1, spw, w2);
    k_filt1<<<48, 256>>>(cw0, cw1, cw2);
    k_filt2<<<3*128*4, 128>>>();
    k_zero<<<1, 256>>>();
    k_pw1<<<dim3(128,Bb), 256, SM_PW1>>>(x, s1, b1, bng, bnb, bnm, bnv);
    k_mlp<<<1, 512, SM_MLP>>>(fc1, fc2, msc, mbi);
    k_fft<<<Bb*Mm, 512, SM_FFT>>>();
    k_pw2<<<dim3(128,Bb), 256, SM_PW2>>>(out);
}

// round 9
// speedup vs baseline: 1.0111x; 1.0111x over previous
#include <cuda_runtime.h>
#include <math.h>

#define DINLINE __device__ __forceinline__

// ---------------- problem constants ----------------
#define Bb 8
#define Hh 128
#define Ww 128
#define Cc 96
#define Mm 192
#define SPEC (128*65)
#define INV_HW (1.0f/16384.0f)

// ---------------- device scratch ----------------
__device__ float  g_xpre[(size_t)Bb*Mm*Hh*Ww];     // reused in-place for xsp
__device__ float2 g_filt[(size_t)3*Mm*SPEC];       // resized filters (BR h order)
__device__ float2 g_tmp[(size_t)48*65*Mm];         // separable-resize intermediate
__device__ float  g_r[Bb*3*Mm];
__device__ float  g_stats[Bb*144];
// tf32-split weights: rows 0..191 = w1, rows 192..239 = spw
__device__ float  g_w1hi[240*96], g_w1lo[240*96];
__device__ float  g_w2hi[96*192], g_w2lo[96*192];

extern __shared__ __align__(16) char SMEM[];

// ---------------- helpers ----------------
DINLINE int br7(int p){ return (int)(__brev((unsigned)p)>>25); }
DINLINE float2 cmulf(float2 a, float2 b){ return make_float2(a.x*b.x - a.y*b.y, a.x*b.y + a.y*b.x); }
DINLINE float2 f2add(float2 a,float2 b){ return make_float2(a.x+b.x, a.y+b.y); }
DINLINE float2 f2sub(float2 a,float2 b){ return make_float2(a.x-b.x, a.y-b.y); }
DINLINE float2 shflx(float2 v,int m){
    v.x = __shfl_xor_sync(0xffffffffu, v.x, m);
    v.y = __shfl_xor_sync(0xffffffffu, v.y, m);
    return v;
}
// tf32 helpers
DINLINE unsigned f2tf(float x){ unsigned r; asm("cvt.rna.tf32.f32 %0,%1;":"=r"(r):"f"(x)); return r; }
DINLINE void tfsplit(float x, unsigned& hi, unsigned& lo){
    hi = f2tf(x);
    lo = f2tf(x - __uint_as_float(hi));
}
DINLINE void mma8(float c[4], const unsigned a[4], unsigned b0, unsigned b1){
    asm("mma.sync.aligned.m16n8k8.row.col.f32.tf32.tf32.f32 "
        "{%0,%1,%2,%3},{%4,%5,%6,%7},{%8,%9},{%0,%1,%2,%3};"
        : "+f"(c[0]),"+f"(c[1]),"+f"(c[2]),"+f"(c[3])
        : "r"(a[0]),"r"(a[1]),"r"(a[2]),"r"(a[3]),"r"(b0),"r"(b1));
}

// Forward DIF 128-pt FFT
DINLINE void fft128_dif(float2 z[4], const float2* tw, int lane){
    #pragma unroll
    for(int j=0;j<2;j++){
        int k=j*32+lane;
        float2 u=z[j], v=z[j+2];
        z[j]=f2add(u,v);
        z[j+2]=cmulf(f2sub(u,v), tw[k]);
    }
    {
        float2 w=tw[2*lane];
        float2 u=z[0],v=z[1];
        z[0]=f2add(u,v); z[1]=cmulf(f2sub(u,v),w);
        u=z[2]; v=z[3];
        z[2]=f2add(u,v); z[3]=cmulf(f2sub(u,v),w);
    }
    #pragma unroll
    for(int d=16; d>=1; d>>=1){
        int k=lane&(d-1);
        float2 w=tw[k*(64/d)];
        bool up=(lane&d)!=0;
        #pragma unroll
        for(int j=0;j<4;j++){
            float2 o=shflx(z[j],d);
            float2 r;
            if(up) r=cmulf(make_float2(o.x - z[j].x, o.y - z[j].y), w);
            else   r=make_float2(z[j].x+o.x, z[j].y+o.y);
            z[j]=r;
        }
    }
}

// DIT 128-pt FFT
template<bool CONJ>
DINLINE void fft128_dit(float2 z[4], const float2* tw, int lane){
    #pragma unroll
    for(int d=1; d<=16; d<<=1){
        int k=lane&(d-1);
        float2 w=tw[k*(64/d)];
        if(CONJ) w.y=-w.y;
        bool up=(lane&d)!=0;
        #pragma unroll
        for(int j=0;j<4;j++){
            float2 o=shflx(z[j],d);
            float2 r;
            if(up){
                float2 t=cmulf(w, z[j]);
                r=make_float2(o.x-t.x, o.y-t.y);
            } else {
                float2 t=cmulf(w, o);
                r=make_float2(z[j].x+t.x, z[j].y+t.y);
            }
            z[j]=r;
        }
    }
    {
        float2 w=tw[2*lane]; if(CONJ) w.y=-w.y;
        float2 t=cmulf(w,z[1]); float2 u=z[0];
        z[0]=f2add(u,t); z[1]=f2sub(u,t);
        t=cmulf(w,z[3]); u=z[2];
        z[2]=f2add(u,t); z[3]=f2sub(u,t);
    }
    #pragma unroll
    for(int j=0;j<2;j++){
        int k=j*32+lane;
        float2 w=tw[k]; if(CONJ) w.y=-w.y;
        float2 t=cmulf(w,z[j+2]); float2 u=z[j];
        z[j]=f2add(u,t);
        z[j+2]=f2sub(u,t);
    }
}

// ---------------- bicubic resize taps ----------------
DINLINE double cubicw(double t){
    t = fabs(t);
    const double a = -0.75;
    if(t <= 1.0) return ((a+2.0)*t - (a+3.0))*t*t + 1.0;
    if(t <  2.0) return a*(((t-5.0)*t+8.0)*t-4.0);
    return 0.0;
}
DINLINE void taps4(int j, int oldn, int newn, int* idx, float* wt){
    double s = (newn > 1) ? (double)j * (double)(oldn-1) / (double)(newn-1) : 0.0;
    int f = (int)floor(s);
    #pragma unroll
    for(int k=0;k<4;k++){
        int kk = f + k - 1;
        idx[k] = min(max(kk, 0), oldn-1);
        wt[k]  = (float)cubicw(s - (double)kk);
    }
}

__constant__ int c_SH[3]={16,8,24};
__constant__ int c_SW[3]={9,4,13};
__constant__ int c_RB[3]={0,16,24};

// ---------------- k_prep ----------------
__global__ void __launch_bounds__(256) k_prep(const float* __restrict__ w1,
                                              const float* __restrict__ spw,
                                              const float* __restrict__ w2){
    int tid=blockIdx.x*256+threadIdx.x;
    for(int i=tid;i<240*96;i+=256*32){
        int n=i/96, k=i%96;
        float w = (n<192)? w1[n*96+k] : spw[(n-192)*96+k];
        unsigned hi,lo; tfsplit(w,hi,lo);
        g_w1hi[i]=__uint_as_float(hi);
        g_w1lo[i]=__uint_as_float(lo);
    }
    for(int i=tid;i<96*192;i+=256*32){
        float w = w2[i];
        unsigned hi,lo; tfsplit(w,hi,lo);
        g_w2hi[i]=__uint_as_float(hi);
        g_w2lo[i]=__uint_as_float(lo);
    }
}

// ---------------- k_filt1 ----------------
__global__ void __launch_bounds__(256) k_filt1(const float* __restrict__ cw0,
                                               const float* __restrict__ cw1,
                                               const float* __restrict__ cw2){
    __shared__ int   widx[65][4];
    __shared__ float wwt [65][4];
    __shared__ float2 rowb[13*Mm];
    int r = blockIdx.x;
    int s = (r<16)?0:((r<24)?1:2);
    int ih = r - c_RB[s];
    int ow = c_SW[s];
    const float* cws = (s==0)?cw0:((s==1)?cw1:cw2);
    int tid=threadIdx.x;
    if(tid<65) taps4(tid, ow, 65, widx[tid], wwt[tid]);
    const float2* src = (const float2*)(cws) + (size_t)ih*ow*Mm;
    for(int i=tid;i<ow*Mm;i+=256) rowb[i]=src[i];
    __syncthreads();
    float2* dst = g_tmp + (size_t)r*65*Mm;
    for(int e=tid;e<65*Mm;e+=256){
        int w=e/Mm, m=e%Mm;
        float ax=0.f, ay=0.f;
        #pragma unroll
        for(int a=0;a<4;a++){
            float wg=wwt[w][a];
            float2 v=rowb[widx[w][a]*Mm+m];
            ax+=wg*v.x; ay+=wg*v.y;
        }
        dst[e]=make_float2(ax,ay);
    }
}

// ---------------- k_filt2 ----------------
__global__ void __launch_bounds__(128) k_filt2(){
    __shared__ int   hidx[4];
    __shared__ float hwt [4];
    __shared__ float2 tile[48*65];
    int bid=blockIdx.x;
    int s  = bid/512;
    int rem= bid%512;
    int hq = rem/4;
    int m0 = (rem%4)*48;
    int tid=threadIdx.x;
    if(tid==0){
        int id[4]; float wt[4];
        taps4(hq, c_SH[s], 128, id, wt);
        #pragma unroll
        for(int a=0;a<4;a++){ hidx[a]=id[a]; hwt[a]=wt[a]; }
    }
    __syncthreads();
    const float2* base = g_tmp + (size_t)c_RB[s]*65*Mm;
    for(int e=tid;e<65*48;e+=128){
        int w=e/48, mm=e%48;
        int m=m0+mm;
        float ax=0.f, ay=0.f;
        #pragma unroll
        for(int a=0;a<4;a++){
            float2 v=base[(size_t)hidx[a]*65*Mm + w*Mm + m];
            ax+=hwt[a]*v.x; ay+=hwt[a]*v.y;
        }
        tile[mm*65+w]=make_float2(ax,ay);
    }
    __syncthreads();
    int hb=br7(hq);
    for(int e=tid;e<48*65;e+=128){
        int mm=e/65, w=e%65;
        g_filt[(size_t)(s*Mm+m0+mm)*SPEC + hb*65 + w]=tile[mm*65+w];
    }
}

// ---------------- k_zero ----------------
__global__ void k_zero(){
    for(int i=threadIdx.x;i<Bb*144;i+=blockDim.x) g_stats[i]=0.f;
}

// ---------------- k_pw1: tf32 MMA pwconv1+Soa + routing stats (staged writeback) ----------------
// smem floats: xs[128*100]=12800, wsh[240*52]=12480, wsl[240*52]=12480,
//              sb[48*132]=6336, bnp[96], red[192]
// after MMA: region [0 .. 37760) reused as outs[192*132]=25344
#define P1_XS  0
#define P1_WH  (P1_XS+12800)
#define P1_WL  (P1_WH+12480)
#define P1_SB  (P1_WL+12480)
#define P1_BNP (P1_SB+6336)
#define P1_RED (P1_BNP+96)
#define P1_TOT (P1_RED+192)
__global__ void __launch_bounds__(256) k_pw1(const float* __restrict__ x,
                                             const float* __restrict__ s1,
                                             const float* __restrict__ b1,
                                             const float* __restrict__ bng,
                                             const float* __restrict__ bnb,
                                             const float* __restrict__ bnm,
                                             const float* __restrict__ bnv){
    float* S=(float*)SMEM;
    float* xs  = S+P1_XS;      // [128][100]
    float* wsh = S+P1_WH;      // [240][52]
    float* wsl = S+P1_WL;
    float* sb  = S+P1_SB;      // [48][132]
    float* bnp = S+P1_BNP;
    float* red = S+P1_RED;
    int tid=threadIdx.x;
    int b=blockIdx.y, pix0=blockIdx.x*128;
    const float* xb = x + ((size_t)b*16384 + pix0)*96;
    for(int i=tid;i<128*96;i+=256){ int p=i/96,c=i%96; xs[p*100+c]=xb[i]; }
    if(tid<48){
        float sc=rsqrtf(bnv[tid]+1e-5f)*bng[tid];
        bnp[tid]=sc;
        bnp[48+tid]=bnb[tid]-bnm[tid]*sc;
    }
    int warp=tid>>5, lane=tid&31;
    int gid=lane>>2, tig=lane&3;
    int pr0=warp*16;
    float C[30][4];
    #pragma unroll
    for(int n=0;n<30;n++){ C[n][0]=0.f;C[n][1]=0.f;C[n][2]=0.f;C[n][3]=0.f; }
    for(int kh=0;kh<2;kh++){
        __syncthreads();
        for(int i=tid;i<240*48;i+=256){
            int n=i/48, kk=i%48;
            wsh[n*52+kk]=g_w1hi[n*96 + kh*48 + kk];
            wsl[n*52+kk]=g_w1lo[n*96 + kh*48 + kk];
        }
        __syncthreads();
        unsigned ah[6][4], al[6][4];
        #pragma unroll
        for(int kt=0;kt<6;kt++){
            int k0=kh*48+kt*8;
            float r0=xs[(pr0+gid  )*100 + k0+tig];
            float r1=xs[(pr0+gid+8)*100 + k0+tig];
            float r2=xs[(pr0+gid  )*100 + k0+tig+4];
            float r3=xs[(pr0+gid+8)*100 + k0+tig+4];
            tfsplit(r0,ah[kt][0],al[kt][0]);
            tfsplit(r1,ah[kt][1],al[kt][1]);
            tfsplit(r2,ah[kt][2],al[kt][2]);
            tfsplit(r3,ah[kt][3],al[kt][3]);
        }
        #pragma unroll 1
        for(int n=0;n<30;n++){
            int nrow=(n*8+gid)*52;
            #pragma unroll
            for(int kt=0;kt<6;kt++){
                int kk=kt*8;
                unsigned b0h=__float_as_uint(wsh[nrow+kk+tig]);
                unsigned b1h=__float_as_uint(wsh[nrow+kk+tig+4]);
                unsigned b0l=__float_as_uint(wsl[nrow+kk+tig]);
                unsigned b1l=__float_as_uint(wsl[nrow+kk+tig+4]);
                mma8(C[n], ah[kt], b0h, b1h);
                mma8(C[n], al[kt], b0h, b1h);
                mma8(C[n], ah[kt], b0l, b1l);
            }
        }
    }
    // gctx sums from xs BEFORE region reuse
    float gsum=0.f;
    if(tid<96){
        #pragma unroll 4
        for(int p=0;p<128;p++) gsum+=xs[p*100+tid];
    }
    // sctx rows -> sb (separate region, safe)
    #pragma unroll
    for(int n=24;n<30;n++){
        int sc=(n-24)*8+2*tig;
        int p=pr0+gid;
        sb[sc*132+p]      =C[n][0];
        sb[(sc+1)*132+p]  =C[n][1];
        sb[sc*132+p+8]    =C[n][2];
        sb[(sc+1)*132+p+8]=C[n][3];
    }
    float scb=*s1, bib=*b1;
    __syncthreads();
    // stage m<192 outputs (Soa applied) into outs[192][132] (reuse xs/wsh/wsl)
    float* outs = S;   // 192*132 = 25344 floats < 37760
    #pragma unroll
    for(int n=0;n<24;n++){
        int mch=n*8+2*tig;
        int p=pr0+gid;
        float v0=fmaxf(C[n][0],0.f), v1=fmaxf(C[n][1],0.f);
        float v2=fmaxf(C[n][2],0.f), v3=fmaxf(C[n][3],0.f);
        outs[mch*132+p]      =scb*v0*v0+bib;
        outs[(mch+1)*132+p]  =scb*v1*v1+bib;
        outs[mch*132+p+8]    =scb*v2*v2+bib;
        outs[(mch+1)*132+p+8]=scb*v3*v3+bib;
    }
    if(tid<96) atomicAdd(&g_stats[b*144+tid], gsum);
    __syncthreads();
    // coalesced write to g_xpre
    float* op = g_xpre + (size_t)b*Mm*16384 + pix0;
    for(int i=tid;i<192*128;i+=256){
        int mm=i>>7, p=i&127;
        op[(size_t)mm*16384+p]=outs[mm*132+p];
    }
    // sctx reduce
    if(tid<192){
        int sc=tid>>2, q=tid&3;
        float scale=bnp[sc], shift=bnp[48+sc];
        float s=0.f;
        #pragma unroll 4
        for(int p=q*32;p<q*32+32;p++) s+=fmaxf(sb[sc*132+p]*scale+shift,0.f);
        red[sc*4+q]=s;
    }
    __syncthreads();
    if(tid<48) atomicAdd(&g_stats[b*144+96+tid], red[4*tid]+red[4*tid+1]+red[4*tid+2]+red[4*tid+3]);
}

// ---------------- k_mlp ----------------
#define MLP_SF   0
#define MLP_FC1  (8*145)
#define MLP_HM   (MLP_FC1+36*145)
#define MLP_FC2  (MLP_HM+8*37)
#define MLP_TOT  (MLP_FC2+576*37)
__global__ void __launch_bounds__(512) k_mlp(const float* __restrict__ fc1,
                                             const float* __restrict__ fc2,
                                             const float* __restrict__ msc,
                                             const float* __restrict__ mbi){
    float* S=(float*)SMEM;
    float* sf  = S+MLP_SF;
    float* f1s = S+MLP_FC1;
    float* hm  = S+MLP_HM;
    float* f2s = S+MLP_FC2;
    int tid=threadIdx.x;
    for(int i=tid;i<8*144;i+=512){ int b=i/144,k=i%144; sf[b*145+k]=g_stats[i]*(1.f/16384.f); }
    for(int i=tid;i<36*144;i+=512){ int j=i/144,k=i%144; f1s[j*145+k]=fc1[i]; }
    for(int i=tid;i<576*36;i+=512){ int j=i/36,k=i%36; f2s[j*37+k]=fc2[i]; }
    __syncthreads();
    if(tid<288){
        int b=tid/36, j=tid%36;
        float a=0.f;
        #pragma unroll 8
        for(int k=0;k<144;k++) a+=sf[b*145+k]*f1s[j*145+k];
        float r=fmaxf(a,0.f);
        hm[b*37+j]=(*msc)*r*r + (*mbi);
    }
    __syncthreads();
    for(int idx=tid; idx<8*Mm; idx+=512){
        int b=idx/Mm, m=idx%Mm;
        float lg[3];
        #pragma unroll
        for(int s=0;s<3;s++){
            float a=0.f;
            const float* f2=f2s+(size_t)(s*Mm+m)*37;
            #pragma unroll
            for(int k=0;k<36;k++) a+=hm[b*37+k]*f2[k];
            lg[s]=a;
        }
        float mx=fmaxf(lg[0],fmaxf(lg[1],lg[2]));
        float e0=expf(lg[0]-mx), e1=expf(lg[1]-mx), e2=expf(lg[2]-mx);
        float inv=1.f/(e0+e1+e2);
        g_r[(b*3+0)*Mm+m]=e0*inv;
        g_r[(b*3+1)*Mm+m]=e1*inv;
        g_r[(b*3+2)*Mm+m]=e2*inv;
    }
}

// ---------------- k_fft (512 thr) ----------------
__global__ void __launch_bounds__(512) k_fft(){
    float2* sh=(float2*)SMEM;
    float2* sm = sh;
    float2* tmpAll = sh + SPEC;
    float2* tw = sh + SPEC + 2048;
    int tid=threadIdx.x, lane=tid&31, wid=tid>>5;
    int bm=blockIdx.x;
    int b=bm/Mm, m=bm%Mm;
    float* plane = g_xpre + (size_t)bm*16384;
    if(tid<64){
        float s,c;
        sincospif((float)tid*(1.0f/64.0f), &s, &c);
        tw[tid]=make_float2(c,-s);
    }
    __syncthreads();
    float2* tmp = tmpAll + wid*128;
    for(int pr=wid; pr<64; pr+=16){
        int ra=2*pr, rb=ra+1;
        float2 z[4];
        #pragma unroll
        for(int j=0;j<4;j++){
            int p=j*32+lane, q=br7(p);
            z[j]=make_float2(plane[ra*128+q], plane[rb*128+q]);
        }
        fft128_dit<false>(z,tw,lane);
        #pragma unroll
        for(int j=0;j<4;j++) tmp[j*32+lane]=z[j];
        __syncwarp();
        #pragma unroll
        for(int t=0;t<2;t++){
            int k=t*32+lane;
            float2 Zk=tmp[k], Zc=tmp[(128-k)&127];
            sm[ra*65+k]=make_float2(0.5f*(Zk.x+Zc.x), 0.5f*(Zk.y-Zc.y));
            sm[rb*65+k]=make_float2(0.5f*(Zk.y+Zc.y), 0.5f*(Zc.x-Zk.x));
        }
        if(lane==0){
            float2 Zk=tmp[64];
            sm[ra*65+64]=make_float2(Zk.x,0.f);
            sm[rb*65+64]=make_float2(Zk.y,0.f);
        }
        __syncwarp();
    }
    __syncthreads();
    for(int col=wid; col<65; col+=16){
        float2 z[4];
        #pragma unroll
        for(int j=0;j<4;j++) z[j]=sm[(j*32+lane)*65+col];
        fft128_dif(z,tw,lane);
        #pragma unroll
        for(int j=0;j<4;j++) sm[(j*32+lane)*65+col]=z[j];
    }
    __syncthreads();
    {
        float r0=g_r[(b*3+0)*Mm+m], r1=g_r[(b*3+1)*Mm+m], r2=g_r[(b*3+2)*Mm+m];
        const float2* f0=g_filt + (size_t)(0*Mm+m)*SPEC;
        const float2* f1=g_filt + (size_t)(1*Mm+m)*SPEC;
        const float2* f2=g_filt + (size_t)(2*Mm+m)*SPEC;
        for(int e=tid;e<SPEC;e+=512){
            float2 a=f0[e], bb=f1[e], c=f2[e];
            float2 comb=make_float2(a.x*r0+bb.x*r1+c.x*r2, a.y*r0+bb.y*r1+c.y*r2);
            sm[e]=cmulf(sm[e],comb);
        }
    }
    __syncthreads();
    for(int col=wid; col<65; col+=16){
        float2 z[4];
        #pragma unroll
        for(int j=0;j<4;j++) z[j]=sm[(j*32+lane)*65+col];
        fft128_dit<true>(z,tw,lane);
        #pragma unroll
        for(int j=0;j<4;j++) sm[(j*32+lane)*65+col]=z[j];
    }
    __syncthreads();
    for(int pr=wid; pr<64; pr+=16){
        int ra=2*pr, rb=ra+1;
        float2 z[4];
        #pragma unroll
        for(int j=0;j<4;j++){
            int p=j*32+lane, k=br7(p);
            float2 zz;
            if(k<=64){
                float2 a=sm[ra*65+k], bb=sm[rb*65+k];
                if(k==0||k==64){ a.y=0.f; bb.y=0.f; }
                zz=make_float2(a.x-bb.y, a.y+bb.x);
            } else {
                int kk=128-k;
                float2 a=sm[ra*65+kk], bb=sm[rb*65+kk];
                zz=make_float2(a.x+bb.y, bb.x-a.y);
            }
            z[j]=zz;
        }
        fft128_dit<true>(z,tw,lane);
        #pragma unroll
        for(int j=0;j<4;j++){
            int p=j*32+lane;
            plane[ra*128+p]=z[j].x*INV_HW;
            plane[rb*128+p]=z[j].y*INV_HW;
        }
    }
}

// ---------------- k_pw2: tf32 MMA pwconv2 (staged writeback) ----------------
// smem floats: As[128*196]=25088, wh[96*100]=9600, wl[96*100]=9600
// after MMA: As region reused as outs[128*100]=12800
#define P2_AS  0
#define P2_WH  (P2_AS+25088)
#define P2_WL  (P2_WH+9600)
#define P2_TOT (P2_WL+9600)
__global__ void __launch_bounds__(256) k_pw2(float* __restrict__ out){
    float* S=(float*)SMEM;
    float* As = S+P2_AS;      // [128][196] k-major
    float* wh = S+P2_WH;
    float* wl = S+P2_WL;
    int tid=threadIdx.x;
    int b=blockIdx.y, pix0=blockIdx.x*128;
    const float* ap = g_xpre + (size_t)b*Mm*16384 + pix0;
    for(int i=tid;i<192*128;i+=256){
        int mm=i>>7, p=i&127;
        As[p*196+mm]=ap[(size_t)mm*16384+p];
    }
    int warp=tid>>5, lane=tid&31;
    int gid=lane>>2, tig=lane&3;
    int pr0=warp*16;
    float C[12][4];
    #pragma unroll
    for(int n=0;n<12;n++){ C[n][0]=0.f;C[n][1]=0.f;C[n][2]=0.f;C[n][3]=0.f; }
    for(int kh=0;kh<2;kh++){
        __syncthreads();
        for(int i=tid;i<96*96;i+=256){
            int c=i/96, kk=i%96;
            wh[c*100+kk]=g_w2hi[c*192 + kh*96 + kk];
            wl[c*100+kk]=g_w2lo[c*192 + kh*96 + kk];
        }
        __syncthreads();
        unsigned ah[12][4], al[12][4];
        #pragma unroll
        for(int kt=0;kt<12;kt++){
            int k0=kh*96+kt*8;
            float r0=As[(pr0+gid  )*196 + k0+tig];
            float r1=As[(pr0+gid+8)*196 + k0+tig];
            float r2=As[(pr0+gid  )*196 + k0+tig+4];
            float r3=As[(pr0+gid+8)*196 + k0+tig+4];
            tfsplit(r0,ah[kt][0],al[kt][0]);
            tfsplit(r1,ah[kt][1],al[kt][1]);
            tfsplit(r2,ah[kt][2],al[kt][2]);
            tfsplit(r3,ah[kt][3],al[kt][3]);
        }
        #pragma unroll 1
        for(int n=0;n<12;n++){
            int nrow=(n*8+gid)*100;
            #pragma unroll
            for(int kt=0;kt<12;kt++){
                int kk=kt*8;
                unsigned b0h=__float_as_uint(wh[nrow+kk+tig]);
                unsigned b1h=__float_as_uint(wh[nrow+kk+tig+4]);
                unsigned b0l=__float_as_uint(wl[nrow+kk+tig]);
                unsigned b1l=__float_as_uint(wl[nrow+kk+tig+4]);
                mma8(C[n], ah[kt], b0h, b1h);
                mma8(C[n], al[kt], b0h, b1h);
                mma8(C[n], ah[kt], b0l, b1l);
            }
        }
    }
    __syncthreads();
    // stage into outs[128][100] (reuse As region) then coalesced write
    float* outs=S;
    #pragma unroll
    for(int n=0;n<12;n++){
        int c0=n*8+2*tig;
        int p=pr0+gid;
        outs[p*100+c0]      =C[n][0];
        outs[p*100+c0+1]    =C[n][1];
        outs[(p+8)*100+c0]  =C[n][2];
        outs[(p+8)*100+c0+1]=C[n][3];
    }
    __syncthreads();
    float* op = out + ((size_t)b*16384 + pix0)*96;
    for(int i=tid;i<128*96;i+=256){
        int p=i/96, c=i%96;
        op[i]=outs[p*100+c];
    }
}

// ---------------- launch ----------------
extern "C" void kernel_launch(void* const* d_in, const int* in_sizes, int n_in,
                              void* d_out, int out_size){
    (void)in_sizes; (void)n_in; (void)out_size;
    const float* x   =(const float*)d_in[0];
    const float* w1  =(const float*)d_in[1];
    const float* s1  =(const float*)d_in[2];
    const float* b1  =(const float*)d_in[3];
    const float* cw0 =(const float*)d_in[4];
    const float* cw1 =(const float*)d_in[5];
    const float* cw2 =(const float*)d_in[6];
    const float* spw =(const float*)d_in[7];
    const float* bng =(const float*)d_in[8];
    const float* bnb =(const float*)d_in[9];
    const float* bnm =(const float*)d_in[10];
    const float* bnv =(const float*)d_in[11];
    const float* fc1 =(const float*)d_in[12];
    const float* msc =(const float*)d_in[13];
    const float* mbi =(const float*)d_in[14];
    const float* fc2 =(const float*)d_in[15];
    const float* w2  =(const float*)d_in[16];
    float* out=(float*)d_out;

    const int SM_PW1 = P1_TOT*4;
    const int SM_FFT = (SPEC+2048+64)*8;
    const int SM_PW2 = P2_TOT*4;
    const int SM_MLP = MLP_TOT*4;

    cudaFuncSetAttribute(k_pw1, cudaFuncAttributeMaxDynamicSharedMemorySize, SM_PW1);
    cudaFuncSetAttribute(k_fft, cudaFuncAttributeMaxDynamicSharedMemorySize, SM_FFT);
    cudaFuncSetAttribute(k_pw2, cudaFuncAttributeMaxDynamicSharedMemorySize, SM_PW2);
    cudaFuncSetAttribute(k_mlp, cudaFuncAttributeMaxDynamicSharedMemorySize, SM_MLP);

    k_prep<<<32, 256>>>(w1, spw, w2);
    k_filt1<<<48, 256>>>(cw0, cw1, cw2);
    k_filt2<<<3*128*4, 128>>>();
    k_zero<<<1, 256>>>();
    k_pw1<<<dim3(128,Bb), 256, SM_PW1>>>(x, s1, b1, bng, bnb, bnm, bnv);
    k_mlp<<<1, 512, SM_MLP>>>(fc1, fc2, msc, mbi);
    k_fft<<<Bb*Mm, 512, SM_FFT>>>();
    k_pw2<<<dim3(128,Bb), 256, SM_PW2>>>(out);
}

// round 10
// speedup vs baseline: 1.2398x; 1.2262x over previous
#include <cuda_runtime.h>
#include <math.h>

#define DINLINE __device__ __forceinline__

// ---------------- problem constants ----------------
#define Bb 8
#define Hh 128
#define Ww 128
#define Cc 96
#define Mm 192
#define SPEC (128*65)
#define INV_HW (1.0f/16384.0f)

// ---------------- device scratch ----------------
__device__ float  g_xpre[(size_t)Bb*Mm*Hh*Ww];     // reused in-place for xsp
__device__ float2 g_filt[(size_t)3*Mm*SPEC];       // resized filters (BR h order)
__device__ float2 g_tmp[(size_t)48*65*Mm];         // separable-resize intermediate
__device__ float  g_r[Bb*3*Mm];
__device__ float  g_stats[Bb*144];
// tf32-split weights: rows 0..191 = w1, rows 192..239 = spw
__device__ float  g_w1hi[240*96], g_w1lo[240*96];
__device__ float  g_w2hi[96*192], g_w2lo[96*192];

extern __shared__ __align__(16) char SMEM[];

// ---------------- helpers ----------------
DINLINE int br7(int p){ return (int)(__brev((unsigned)p)>>25); }
DINLINE float2 cmulf(float2 a, float2 b){ return make_float2(a.x*b.x - a.y*b.y, a.x*b.y + a.y*b.x); }
DINLINE float2 f2add(float2 a,float2 b){ return make_float2(a.x+b.x, a.y+b.y); }
DINLINE float2 f2sub(float2 a,float2 b){ return make_float2(a.x-b.x, a.y-b.y); }
DINLINE float2 shflx(float2 v,int m){
    v.x = __shfl_xor_sync(0xffffffffu, v.x, m);
    v.y = __shfl_xor_sync(0xffffffffu, v.y, m);
    return v;
}
// tf32 helpers
DINLINE unsigned f2tf(float x){ unsigned r; asm("cvt.rna.tf32.f32 %0,%1;":"=r"(r):"f"(x)); return r; }
DINLINE void tfsplit(float x, unsigned& hi, unsigned& lo){
    hi = f2tf(x);
    lo = f2tf(x - __uint_as_float(hi));
}
DINLINE void mma8(float c[4], const unsigned a[4], unsigned b0, unsigned b1){
    asm("mma.sync.aligned.m16n8k8.row.col.f32.tf32.tf32.f32 "
        "{%0,%1,%2,%3},{%4,%5,%6,%7},{%8,%9},{%0,%1,%2,%3};"
        : "+f"(c[0]),"+f"(c[1]),"+f"(c[2]),"+f"(c[3])
        : "r"(a[0]),"r"(a[1]),"r"(a[2]),"r"(a[3]),"r"(b0),"r"(b1));
}

// Forward DIF 128-pt FFT
DINLINE void fft128_dif(float2 z[4], const float2* tw, int lane){
    #pragma unroll
    for(int j=0;j<2;j++){
        int k=j*32+lane;
        float2 u=z[j], v=z[j+2];
        z[j]=f2add(u,v);
        z[j+2]=cmulf(f2sub(u,v), tw[k]);
    }
    {
        float2 w=tw[2*lane];
        float2 u=z[0],v=z[1];
        z[0]=f2add(u,v); z[1]=cmulf(f2sub(u,v),w);
        u=z[2]; v=z[3];
        z[2]=f2add(u,v); z[3]=cmulf(f2sub(u,v),w);
    }
    #pragma unroll
    for(int d=16; d>=1; d>>=1){
        int k=lane&(d-1);
        float2 w=tw[k*(64/d)];
        bool up=(lane&d)!=0;
        #pragma unroll
        for(int j=0;j<4;j++){
            float2 o=shflx(z[j],d);
            float2 r;
            if(up) r=cmulf(make_float2(o.x - z[j].x, o.y - z[j].y), w);
            else   r=make_float2(z[j].x+o.x, z[j].y+o.y);
            z[j]=r;
        }
    }
}

// DIT 128-pt FFT
template<bool CONJ>
DINLINE void fft128_dit(float2 z[4], const float2* tw, int lane){
    #pragma unroll
    for(int d=1; d<=16; d<<=1){
        int k=lane&(d-1);
        float2 w=tw[k*(64/d)];
        if(CONJ) w.y=-w.y;
        bool up=(lane&d)!=0;
        #pragma unroll
        for(int j=0;j<4;j++){
            float2 o=shflx(z[j],d);
            float2 r;
            if(up){
                float2 t=cmulf(w, z[j]);
                r=make_float2(o.x-t.x, o.y-t.y);
            } else {
                float2 t=cmulf(w, o);
                r=make_float2(z[j].x+t.x, z[j].y+t.y);
            }
            z[j]=r;
        }
    }
    {
        float2 w=tw[2*lane]; if(CONJ) w.y=-w.y;
        float2 t=cmulf(w,z[1]); float2 u=z[0];
        z[0]=f2add(u,t); z[1]=f2sub(u,t);
        t=cmulf(w,z[3]); u=z[2];
        z[2]=f2add(u,t); z[3]=f2sub(u,t);
    }
    #pragma unroll
    for(int j=0;j<2;j++){
        int k=j*32+lane;
        float2 w=tw[k]; if(CONJ) w.y=-w.y;
        float2 t=cmulf(w,z[j+2]); float2 u=z[j];
        z[j]=f2add(u,t);
        z[j+2]=f2sub(u,t);
    }
}

// ---------------- bicubic resize taps ----------------
DINLINE double cubicw(double t){
    t = fabs(t);
    const double a = -0.75;
    if(t <= 1.0) return ((a+2.0)*t - (a+3.0))*t*t + 1.0;
    if(t <  2.0) return a*(((t-5.0)*t+8.0)*t-4.0);
    return 0.0;
}
DINLINE void taps4(int j, int oldn, int newn, int* idx, float* wt){
    double s = (newn > 1) ? (double)j * (double)(oldn-1) / (double)(newn-1) : 0.0;
    int f = (int)floor(s);
    #pragma unroll
    for(int k=0;k<4;k++){
        int kk = f + k - 1;
        idx[k] = min(max(kk, 0), oldn-1);
        wt[k]  = (float)cubicw(s - (double)kk);
    }
}

__constant__ int c_SH[3]={16,8,24};
__constant__ int c_SW[3]={9,4,13};
__constant__ int c_RB[3]={0,16,24};

// ---------------- k_prep ----------------
__global__ void __launch_bounds__(256) k_prep(const float* __restrict__ w1,
                                              const float* __restrict__ spw,
                                              const float* __restrict__ w2){
    int tid=blockIdx.x*256+threadIdx.x;
    for(int i=tid;i<240*96;i+=256*32){
        int n=i/96, k=i%96;
        float w = (n<192)? w1[n*96+k] : spw[(n-192)*96+k];
        unsigned hi,lo; tfsplit(w,hi,lo);
        g_w1hi[i]=__uint_as_float(hi);
        g_w1lo[i]=__uint_as_float(lo);
    }
    for(int i=tid;i<96*192;i+=256*32){
        float w = w2[i];
        unsigned hi,lo; tfsplit(w,hi,lo);
        g_w2hi[i]=__uint_as_float(hi);
        g_w2lo[i]=__uint_as_float(lo);
    }
}

// ---------------- k_filt1 ----------------
__global__ void __launch_bounds__(256) k_filt1(const float* __restrict__ cw0,
                                               const float* __restrict__ cw1,
                                               const float* __restrict__ cw2){
    __shared__ int   widx[65][4];
    __shared__ float wwt [65][4];
    __shared__ float2 rowb[13*Mm];
    int r = blockIdx.x;
    int s = (r<16)?0:((r<24)?1:2);
    int ih = r - c_RB[s];
    int ow = c_SW[s];
    const float* cws = (s==0)?cw0:((s==1)?cw1:cw2);
    int tid=threadIdx.x;
    if(tid<65) taps4(tid, ow, 65, widx[tid], wwt[tid]);
    const float2* src = (const float2*)(cws) + (size_t)ih*ow*Mm;
    for(int i=tid;i<ow*Mm;i+=256) rowb[i]=src[i];
    __syncthreads();
    float2* dst = g_tmp + (size_t)r*65*Mm;
    for(int e=tid;e<65*Mm;e+=256){
        int w=e/Mm, m=e%Mm;
        float ax=0.f, ay=0.f;
        #pragma unroll
        for(int a=0;a<4;a++){
            float wg=wwt[w][a];
            float2 v=rowb[widx[w][a]*Mm+m];
            ax+=wg*v.x; ay+=wg*v.y;
        }
        dst[e]=make_float2(ax,ay);
    }
}

// ---------------- k_filt2 ----------------
__global__ void __launch_bounds__(128) k_filt2(){
    __shared__ int   hidx[4];
    __shared__ float hwt [4];
    __shared__ float2 tile[48*65];
    int bid=blockIdx.x;
    int s  = bid/512;
    int rem= bid%512;
    int hq = rem/4;
    int m0 = (rem%4)*48;
    int tid=threadIdx.x;
    if(tid==0){
        int id[4]; float wt[4];
        taps4(hq, c_SH[s], 128, id, wt);
        #pragma unroll
        for(int a=0;a<4;a++){ hidx[a]=id[a]; hwt[a]=wt[a]; }
    }
    __syncthreads();
    const float2* base = g_tmp + (size_t)c_RB[s]*65*Mm;
    for(int e=tid;e<65*48;e+=128){
        int w=e/48, mm=e%48;
        int m=m0+mm;
        float ax=0.f, ay=0.f;
        #pragma unroll
        for(int a=0;a<4;a++){
            float2 v=base[(size_t)hidx[a]*65*Mm + w*Mm + m];
            ax+=hwt[a]*v.x; ay+=hwt[a]*v.y;
        }
        tile[mm*65+w]=make_float2(ax,ay);
    }
    __syncthreads();
    int hb=br7(hq);
    for(int e=tid;e<48*65;e+=128){
        int mm=e/65, w=e%65;
        g_filt[(size_t)(s*Mm+m0+mm)*SPEC + hb*65 + w]=tile[mm*65+w];
    }
}

// ---------------- k_zero ----------------
__global__ void k_zero(){
    for(int i=threadIdx.x;i<Bb*144;i+=blockDim.x) g_stats[i]=0.f;
}

// ---------------- k_pw1: tf32 MMA pwconv1+Soa + routing stats ----------------
// Registers: accumulators fully unrolled (NO runtime indexing!), 3-pass per kt
// to break MMA accumulator dependency chains.
#define P1_XS  0
#define P1_WH  (P1_XS+12800)
#define P1_WL  (P1_WH+12480)
#define P1_SB  (P1_WL+12480)
#define P1_BNP (P1_SB+6336)
#define P1_RED (P1_BNP+96)
#define P1_TOT (P1_RED+192)
__global__ void __launch_bounds__(256) k_pw1(const float* __restrict__ x,
                                             const float* __restrict__ s1,
                                             const float* __restrict__ b1,
                                             const float* __restrict__ bng,
                                             const float* __restrict__ bnb,
                                             const float* __restrict__ bnm,
                                             const float* __restrict__ bnv){
    float* S=(float*)SMEM;
    float* xs  = S+P1_XS;      // [128][100]
    float* wsh = S+P1_WH;      // [240][52]
    float* wsl = S+P1_WL;
    float* sb  = S+P1_SB;      // [48][132]
    float* bnp = S+P1_BNP;
    float* red = S+P1_RED;
    int tid=threadIdx.x;
    int b=blockIdx.y, pix0=blockIdx.x*128;
    const float* xb = x + ((size_t)b*16384 + pix0)*96;
    for(int i=tid;i<128*96;i+=256){ int p=i/96,c=i%96; xs[p*100+c]=xb[i]; }
    if(tid<48){
        float sc=rsqrtf(bnv[tid]+1e-5f)*bng[tid];
        bnp[tid]=sc;
        bnp[48+tid]=bnb[tid]-bnm[tid]*sc;
    }
    int warp=tid>>5, lane=tid&31;
    int gid=lane>>2, tig=lane&3;
    int pr0=warp*16;
    float C[30][4];
    #pragma unroll
    for(int n=0;n<30;n++){ C[n][0]=0.f;C[n][1]=0.f;C[n][2]=0.f;C[n][3]=0.f; }
    #pragma unroll 1
    for(int kh=0;kh<2;kh++){
        __syncthreads();
        for(int i=tid;i<240*48;i+=256){
            int n=i/48, kk=i%48;
            wsh[n*52+kk]=g_w1hi[n*96 + kh*48 + kk];
            wsl[n*52+kk]=g_w1lo[n*96 + kh*48 + kk];
        }
        __syncthreads();
        unsigned ah[6][4], al[6][4];
        #pragma unroll
        for(int kt=0;kt<6;kt++){
            int k0=kh*48+kt*8;
            float r0=xs[(pr0+gid  )*100 + k0+tig];
            float r1=xs[(pr0+gid+8)*100 + k0+tig];
            float r2=xs[(pr0+gid  )*100 + k0+tig+4];
            float r3=xs[(pr0+gid+8)*100 + k0+tig+4];
            tfsplit(r0,ah[kt][0],al[kt][0]);
            tfsplit(r1,ah[kt][1],al[kt][1]);
            tfsplit(r2,ah[kt][2],al[kt][2]);
            tfsplit(r3,ah[kt][3],al[kt][3]);
        }
        #pragma unroll
        for(int kt=0;kt<6;kt++){
            int kk=kt*8;
            // pass 1: ah * bh (independent accumulators back-to-back)
            #pragma unroll
            for(int n=0;n<30;n++){
                int nrow=(n*8+gid)*52 + kk;
                unsigned b0=__float_as_uint(wsh[nrow+tig]);
                unsigned b1=__float_as_uint(wsh[nrow+tig+4]);
                mma8(C[n], ah[kt], b0, b1);
            }
            // pass 2: al * bh
            #pragma unroll
            for(int n=0;n<30;n++){
                int nrow=(n*8+gid)*52 + kk;
                unsigned b0=__float_as_uint(wsh[nrow+tig]);
                unsigned b1=__float_as_uint(wsh[nrow+tig+4]);
                mma8(C[n], al[kt], b0, b1);
            }
            // pass 3: ah * bl
            #pragma unroll
            for(int n=0;n<30;n++){
                int nrow=(n*8+gid)*52 + kk;
                unsigned b0=__float_as_uint(wsl[nrow+tig]);
                unsigned b1=__float_as_uint(wsl[nrow+tig+4]);
                mma8(C[n], ah[kt], b0, b1);
            }
        }
    }
    // gctx sums from xs BEFORE region reuse
    float gsum=0.f;
    if(tid<96){
        #pragma unroll 4
        for(int p=0;p<128;p++) gsum+=xs[p*100+tid];
    }
    // sctx rows -> sb
    #pragma unroll
    for(int n=24;n<30;n++){
        int sc=(n-24)*8+2*tig;
        int p=pr0+gid;
        sb[sc*132+p]      =C[n][0];
        sb[(sc+1)*132+p]  =C[n][1];
        sb[sc*132+p+8]    =C[n][2];
        sb[(sc+1)*132+p+8]=C[n][3];
    }
    float scb=*s1, bib=*b1;
    __syncthreads();
    // stage m<192 outputs (Soa applied) into outs[192][132]
    float* outs = S;   // 192*132 = 25344 floats < 37760
    #pragma unroll
    for(int n=0;n<24;n++){
        int mch=n*8+2*tig;
        int p=pr0+gid;
        float v0=fmaxf(C[n][0],0.f), v1=fmaxf(C[n][1],0.f);
        float v2=fmaxf(C[n][2],0.f), v3=fmaxf(C[n][3],0.f);
        outs[mch*132+p]      =scb*v0*v0+bib;
        outs[(mch+1)*132+p]  =scb*v1*v1+bib;
        outs[mch*132+p+8]    =scb*v2*v2+bib;
        outs[(mch+1)*132+p+8]=scb*v3*v3+bib;
    }
    if(tid<96) atomicAdd(&g_stats[b*144+tid], gsum);
    __syncthreads();
    // coalesced write to g_xpre
    float* op = g_xpre + (size_t)b*Mm*16384 + pix0;
    for(int i=tid;i<192*128;i+=256){
        int mm=i>>7, p=i&127;
        op[(size_t)mm*16384+p]=outs[mm*132+p];
    }
    // sctx reduce
    if(tid<192){
        int sc=tid>>2, q=tid&3;
        float scale=bnp[sc], shift=bnp[48+sc];
        float s=0.f;
        #pragma unroll 4
        for(int p=q*32;p<q*32+32;p++) s+=fmaxf(sb[sc*132+p]*scale+shift,0.f);
        red[sc*4+q]=s;
    }
    __syncthreads();
    if(tid<48) atomicAdd(&g_stats[b*144+96+tid], red[4*tid]+red[4*tid+1]+red[4*tid+2]+red[4*tid+3]);
}

// ---------------- k_mlp ----------------
#define MLP_SF   0
#define MLP_FC1  (8*145)
#define MLP_HM   (MLP_FC1+36*145)
#define MLP_FC2  (MLP_HM+8*37)
#define MLP_TOT  (MLP_FC2+576*37)
__global__ void __launch_bounds__(512) k_mlp(const float* __restrict__ fc1,
                                             const float* __restrict__ fc2,
                                             const float* __restrict__ msc,
                                             const float* __restrict__ mbi){
    float* S=(float*)SMEM;
    float* sf  = S+MLP_SF;
    float* f1s = S+MLP_FC1;
    float* hm  = S+MLP_HM;
    float* f2s = S+MLP_FC2;
    int tid=threadIdx.x;
    for(int i=tid;i<8*144;i+=512){ int b=i/144,k=i%144; sf[b*145+k]=g_stats[i]*(1.f/16384.f); }
    for(int i=tid;i<36*144;i+=512){ int j=i/144,k=i%144; f1s[j*145+k]=fc1[i]; }
    for(int i=tid;i<576*36;i+=512){ int j=i/36,k=i%36; f2s[j*37+k]=fc2[i]; }
    __syncthreads();
    if(tid<288){
        int b=tid/36, j=tid%36;
        float a=0.f;
        #pragma unroll 8
        for(int k=0;k<144;k++) a+=sf[b*145+k]*f1s[j*145+k];
        float r=fmaxf(a,0.f);
        hm[b*37+j]=(*msc)*r*r + (*mbi);
    }
    __syncthreads();
    for(int idx=tid; idx<8*Mm; idx+=512){
        int b=idx/Mm, m=idx%Mm;
        float lg[3];
        #pragma unroll
        for(int s=0;s<3;s++){
            float a=0.f;
            const float* f2=f2s+(size_t)(s*Mm+m)*37;
            #pragma unroll
            for(int k=0;k<36;k++) a+=hm[b*37+k]*f2[k];
            lg[s]=a;
        }
        float mx=fmaxf(lg[0],fmaxf(lg[1],lg[2]));
        float e0=expf(lg[0]-mx), e1=expf(lg[1]-mx), e2=expf(lg[2]-mx);
        float inv=1.f/(e0+e1+e2);
        g_r[(b*3+0)*Mm+m]=e0*inv;
        g_r[(b*3+1)*Mm+m]=e1*inv;
        g_r[(b*3+2)*Mm+m]=e2*inv;
    }
}

// ---------------- k_fft (512 thr) ----------------
__global__ void __launch_bounds__(512) k_fft(){
    float2* sh=(float2*)SMEM;
    float2* sm = sh;
    float2* tmpAll = sh + SPEC;
    float2* tw = sh + SPEC + 2048;
    int tid=threadIdx.x, lane=tid&31, wid=tid>>5;
    int bm=blockIdx.x;
    int b=bm/Mm, m=bm%Mm;
    float* plane = g_xpre + (size_t)bm*16384;
    if(tid<64){
        float s,c;
        sincospif((float)tid*(1.0f/64.0f), &s, &c);
        tw[tid]=make_float2(c,-s);
    }
    __syncthreads();
    float2* tmp = tmpAll + wid*128;
    for(int pr=wid; pr<64; pr+=16){
        int ra=2*pr, rb=ra+1;
        float2 z[4];
        #pragma unroll
        for(int j=0;j<4;j++){
            int p=j*32+lane, q=br7(p);
            z[j]=make_float2(plane[ra*128+q], plane[rb*128+q]);
        }
        fft128_dit<false>(z,tw,lane);
        #pragma unroll
        for(int j=0;j<4;j++) tmp[j*32+lane]=z[j];
        __syncwarp();
        #pragma unroll
        for(int t=0;t<2;t++){
            int k=t*32+lane;
            float2 Zk=tmp[k], Zc=tmp[(128-k)&127];
            sm[ra*65+k]=make_float2(0.5f*(Zk.x+Zc.x), 0.5f*(Zk.y-Zc.y));
            sm[rb*65+k]=make_float2(0.5f*(Zk.y+Zc.y), 0.5f*(Zc.x-Zk.x));
        }
        if(lane==0){
            float2 Zk=tmp[64];
            sm[ra*65+64]=make_float2(Zk.x,0.f);
            sm[rb*65+64]=make_float2(Zk.y,0.f);
        }
        __syncwarp();
    }
    __syncthreads();
    for(int col=wid; col<65; col+=16){
        float2 z[4];
        #pragma unroll
        for(int j=0;j<4;j++) z[j]=sm[(j*32+lane)*65+col];
        fft128_dif(z,tw,lane);
        #pragma unroll
        for(int j=0;j<4;j++) sm[(j*32+lane)*65+col]=z[j];
    }
    __syncthreads();
    {
        float r0=g_r[(b*3+0)*Mm+m], r1=g_r[(b*3+1)*Mm+m], r2=g_r[(b*3+2)*Mm+m];
        const float2* f0=g_filt + (size_t)(0*Mm+m)*SPEC;
        const float2* f1=g_filt + (size_t)(1*Mm+m)*SPEC;
        const float2* f2=g_filt + (size_t)(2*Mm+m)*SPEC;
        for(int e=tid;e<SPEC;e+=512){
            float2 a=f0[e], bb=f1[e], c=f2[e];
            float2 comb=make_float2(a.x*r0+bb.x*r1+c.x*r2, a.y*r0+bb.y*r1+c.y*r2);
            sm[e]=cmulf(sm[e],comb);
        }
    }
    __syncthreads();
    for(int col=wid; col<65; col+=16){
        float2 z[4];
        #pragma unroll
        for(int j=0;j<4;j++) z[j]=sm[(j*32+lane)*65+col];
        fft128_dit<true>(z,tw,lane);
        #pragma unroll
        for(int j=0;j<4;j++) sm[(j*32+lane)*65+col]=z[j];
    }
    __syncthreads();
    for(int pr=wid; pr<64; pr+=16){
        int ra=2*pr, rb=ra+1;
        float2 z[4];
        #pragma unroll
        for(int j=0;j<4;j++){
            int p=j*32+lane, k=br7(p);
            float2 zz;
            if(k<=64){
                float2 a=sm[ra*65+k], bb=sm[rb*65+k];
                if(k==0||k==64){ a.y=0.f; bb.y=0.f; }
                zz=make_float2(a.x-bb.y, a.y+bb.x);
            } else {
                int kk=128-k;
                float2 a=sm[ra*65+kk], bb=sm[rb*65+kk];
                zz=make_float2(a.x+bb.y, bb.x-a.y);
            }
            z[j]=zz;
        }
        fft128_dit<true>(z,tw,lane);
        #pragma unroll
        for(int j=0;j<4;j++){
            int p=j*32+lane;
            plane[ra*128+p]=z[j].x*INV_HW;
            plane[rb*128+p]=z[j].y*INV_HW;
        }
    }
}

// ---------------- k_pw2: tf32 MMA pwconv2 (unrolled, 3-pass) ----------------
#define P2_AS  0
#define P2_WH  (P2_AS+25088)
#define P2_WL  (P2_WH+9600)
#define P2_TOT (P2_WL+9600)
__global__ void __launch_bounds__(256) k_pw2(float* __restrict__ out){
    float* S=(float*)SMEM;
    float* As = S+P2_AS;      // [128][196] k-major
    float* wh = S+P2_WH;
    float* wl = S+P2_WL;
    int tid=threadIdx.x;
    int b=blockIdx.y, pix0=blockIdx.x*128;
    const float* ap = g_xpre + (size_t)b*Mm*16384 + pix0;
    for(int i=tid;i<192*128;i+=256){
        int mm=i>>7, p=i&127;
        As[p*196+mm]=ap[(size_t)mm*16384+p];
    }
    int warp=tid>>5, lane=tid&31;
    int gid=lane>>2, tig=lane&3;
    int pr0=warp*16;
    float C[12][4];
    #pragma unroll
    for(int n=0;n<12;n++){ C[n][0]=0.f;C[n][1]=0.f;C[n][2]=0.f;C[n][3]=0.f; }
    #pragma unroll 1
    for(int kh=0;kh<2;kh++){
        __syncthreads();
        for(int i=tid;i<96*96;i+=256){
            int c=i/96, kk=i%96;
            wh[c*100+kk]=g_w2hi[c*192 + kh*96 + kk];
            wl[c*100+kk]=g_w2lo[c*192 + kh*96 + kk];
        }
        __syncthreads();
        unsigned ah[12][4], al[12][4];
        #pragma unroll
        for(int kt=0;kt<12;kt++){
            int k0=kh*96+kt*8;
            float r0=As[(pr0+gid  )*196 + k0+tig];
            float r1=As[(pr0+gid+8)*196 + k0+tig];
            float r2=As[(pr0+gid  )*196 + k0+tig+4];
            float r3=As[(pr0+gid+8)*196 + k0+tig+4];
            tfsplit(r0,ah[kt][0],al[kt][0]);
            tfsplit(r1,ah[kt][1],al[kt][1]);
            tfsplit(r2,ah[kt][2],al[kt][2]);
            tfsplit(r3,ah[kt][3],al[kt][3]);
        }
        #pragma unroll
        for(int kt=0;kt<12;kt++){
            int kk=kt*8;
            #pragma unroll
            for(int n=0;n<12;n++){
                int nrow=(n*8+gid)*100 + kk;
                unsigned b0=__float_as_uint(wh[nrow+tig]);
                unsigned b1=__float_as_uint(wh[nrow+tig+4]);
                mma8(C[n], ah[kt], b0, b1);
            }
            #pragma unroll
            for(int n=0;n<12;n++){
                int nrow=(n*8+gid)*100 + kk;
                unsigned b0=__float_as_uint(wh[nrow+tig]);
                unsigned b1=__float_as_uint(wh[nrow+tig+4]);
                mma8(C[n], al[kt], b0, b1);
            }
            #pragma unroll
            for(int n=0;n<12;n++){
                int nrow=(n*8+gid)*100 + kk;
                unsigned b0=__float_as_uint(wl[nrow+tig]);
                unsigned b1=__float_as_uint(wl[nrow+tig+4]);
                mma8(C[n], ah[kt], b0, b1);
            }
        }
    }
    __syncthreads();
    // stage into outs[128][100] then coalesced write
    float* outs=S;
    #pragma unroll
    for(int n=0;n<12;n++){
        int c0=n*8+2*tig;
        int p=pr0+gid;
        outs[p*100+c0]      =C[n][0];
        outs[p*100+c0+1]    =C[n][1];
        outs[(p+8)*100+c0]  =C[n][2];
        outs[(p+8)*100+c0+1]=C[n][3];
    }
    __syncthreads();
    float* op = out + ((size_t)b*16384 + pix0)*96;
    for(int i=tid;i<128*96;i+=256){
        int p=i/96, c=i%96;
        op[i]=outs[p*100+c];
    }
}

// ---------------- launch ----------------
extern "C" void kernel_launch(void* const* d_in, const int* in_sizes, int n_in,
                              void* d_out, int out_size){
    (void)in_sizes; (void)n_in; (void)out_size;
    const float* x   =(const float*)d_in[0];
    const float* w1  =(const float*)d_in[1];
    const float* s1  =(const float*)d_in[2];
    const float* b1  =(const float*)d_in[3];
    const float* cw0 =(const float*)d_in[4];
    const float* cw1 =(const float*)d_in[5];
    const float* cw2 =(const float*)d_in[6];
    const float* spw =(const float*)d_in[7];
    const float* bng =(const float*)d_in[8];
    const float* bnb =(const float*)d_in[9];
    const float* bnm =(const float*)d_in[10];
    const float* bnv =(const float*)d_in[11];
    const float* fc1 =(const float*)d_in[12];
    const float* msc =(const float*)d_in[13];
    const float* mbi =(const float*)d_in[14];
    const float* fc2 =(const float*)d_in[15];
    const float* w2  =(const float*)d_in[16];
    float* out=(float*)d_out;

    const int SM_PW1 = P1_TOT*4;
    const int SM_FFT = (SPEC+2048+64)*8;
    const int SM_PW2 = P2_TOT*4;
    const int SM_MLP = MLP_TOT*4;

    cudaFuncSetAttribute(k_pw1, cudaFuncAttributeMaxDynamicSharedMemorySize, SM_PW1);
    cudaFuncSetAttribute(k_fft, cudaFuncAttributeMaxDynamicSharedMemorySize, SM_FFT);
    cudaFuncSetAttribute(k_pw2, cudaFuncAttributeMaxDynamicSharedMemorySize, SM_PW2);
    cudaFuncSetAttribute(k_mlp, cudaFuncAttributeMaxDynamicSharedMemorySize, SM_MLP);

    k_prep<<<32, 256>>>(w1, spw, w2);
    k_filt1<<<48, 256>>>(cw0, cw1, cw2);
    k_filt2<<<3*128*4, 128>>>();
    k_zero<<<1, 256>>>();
    k_pw1<<<dim3(128,Bb), 256, SM_PW1>>>(x, s1, b1, bng, bnb, bnm, bnv);
    k_mlp<<<1, 512, SM_MLP>>>(fc1, fc2, msc, mbi);
    k_fft<<<Bb*Mm, 512, SM_FFT>>>();
    k_pw2<<<dim3(128,Bb), 256, SM_PW2>>>(out);
}